// round 7
// baseline (speedup 1.0000x reference)
#include <cuda_runtime.h>
#include <cstdint>

#define T_LEN 1024
#define B_SZ  64
#define D_DIM 512
#define N_TAG 24

// Output layout (float32): decoded | pot | lens | trans
#define OFF_POT   (B_SZ * T_LEN)                     // 65536
#define OFF_LENS  (OFF_POT + B_SZ * T_LEN * N_TAG)   // 1638400
#define OFF_TRANS (OFF_LENS + B_SZ)                  // 1638464

typedef unsigned long long u64;

// Packed f32x2 FMA (sm_103a FFMA2 — PTX only)
__device__ __forceinline__ u64 ffma2(u64 a, u64 b, u64 c) {
    u64 d;
    asm("fma.rn.f32x2 %0, %1, %2, %3;" : "=l"(d) : "l"(a), "l"(b), "l"(c));
    return d;
}

struct __align__(16) f4u { u64 lo, hi; };   // one LDS.128 = 2 k-pairs

// ---------------------------------------------------------------------------
// GEMM: pot = x @ W + b (+ boundaries).
// Persistent grid 148 x 256 threads (8 warps = 2/SMSP). Tile = 128 rows,
// thread = 1 row x 12 tags, 512 tiles strided over blocks.
// Per 4-k chunk: 12 broadcast W-LDS.128 + 1 x-LDS.128 + 24 FFMA2.
// ---------------------------------------------------------------------------
#define KT        32               // k-floats per x tile
#define NKT       (D_DIM / KT)     // 16
#define XS_STRIDE 18               // u64 per row: 8 float4 data + 1 pad
#define WTAG_F4U  (D_DIM / 4)      // f4u per tag row = 128
#define TILE_ROWS 128
#define NTILES    (B_SZ * T_LEN / TILE_ROWS)   // 512
#define GRID_GEMM 148

extern __shared__ u64 dyn_smem[];

__global__ void __launch_bounds__(256)
gemm_pot_kernel(const float* __restrict__ x,
                const float* __restrict__ W,
                const float* __restrict__ bias,
                const float* __restrict__ lb,
                const float* __restrict__ rb,
                float* __restrict__ potOut) {
    u64* Ws = dyn_smem;                        // [24][256] u64 (tag-major)
    u64* xs = dyn_smem + N_TAG * (D_DIM / 2);  // [128][XS_STRIDE] u64
    float* Wsf = (float*)Ws;

    int tid = threadIdx.x;

    // W transposed into SMEM once per block: Wsf[n*512 + k] = W[k*24 + n]
    for (int i = tid; i < D_DIM * N_TAG; i += 256) {
        int k = i / N_TAG;
        int n = i - k * N_TAG;
        Wsf[n * D_DIM + k] = W[i];
    }

    int rslot = tid & 127;          // row within tile
    int h     = tid >> 7;           // tag half: tags [12h, 12h+12)

    float bb[12], lbb[12], rbb[12];
#pragma unroll
    for (int i = 0; i < 12; i++) {
        int n = h * 12 + i;
        bb[i]  = bias[n];
        lbb[i] = lb[n];
        rbb[i] = rb[n];
    }

    const f4u* xrow = (const f4u*)(xs + rslot * XS_STRIDE);
    const f4u* wb   = (const f4u*)(Ws + (h * 12) * (D_DIM / 2));

    for (int tile = blockIdx.x; tile < NTILES; tile += GRID_GEMM) {
        int rowg = tile * TILE_ROWS;
        const float4* x4g = (const float4*)x + (size_t)rowg * (D_DIM / 4);

        u64 acc[12];
#pragma unroll
        for (int i = 0; i < 12; i++) acc[i] = 0ull;

        for (int kt = 0; kt < NKT; kt++) {
            __syncthreads();   // previous k-tile readers done (and W on entry)
            // Stage x tile: 128 rows x 8 float4, coalesced (4 per thread)
#pragma unroll
            for (int j = 0; j < 4; j++) {
                int idx = tid + j * 256;          // 0..1023
                int row = idx >> 3;
                int c   = idx & 7;
                float4 v = x4g[(size_t)row * (D_DIM / 4) + kt * 8 + c];
                *(float4*)(xs + row * XS_STRIDE + c * 2) = v;
            }
            __syncthreads();

#pragma unroll
            for (int kk2 = 0; kk2 < KT / 4; kk2++) {
                f4u xv = xrow[kk2];
#pragma unroll
                for (int i = 0; i < 12; i++) {
                    f4u wv = wb[i * WTAG_F4U + kt * 8 + kk2];
                    acc[i] = ffma2(xv.lo, wv.lo, acc[i]);
                    acc[i] = ffma2(xv.hi, wv.hi, acc[i]);
                }
            }
        }

        // Epilogue for this tile
        int r = rowg + rslot;
        int t = r & (T_LEN - 1);
        float v[12];
#pragma unroll
        for (int i = 0; i < 12; i++) {
            float lo = __uint_as_float((unsigned)(acc[i] & 0xffffffffull));
            float hi = __uint_as_float((unsigned)(acc[i] >> 32));
            float s = lo + hi + bb[i];
            if (t == 0)         s += lbb[i];
            if (t == T_LEN - 1) s += rbb[i];
            v[i] = s;
        }
        float4* outp = (float4*)(potOut + (size_t)r * N_TAG + h * 12);
        outp[0] = make_float4(v[0], v[1], v[2], v[3]);
        outp[1] = make_float4(v[4], v[5], v[6], v[7]);
        outp[2] = make_float4(v[8], v[9], v[10], v[11]);
        __syncthreads();   // keep xs stable until all readers done before next tile
    }
}

// ---------------------------------------------------------------------------
// Viterbi. One warp per batch. pot streamed via double-buffered cp.async.
// Tournament: value via fmaxf (FMNMX, alu pipe, short chain), idx via
// FSETP+SEL on the pre-update predicate. First-occurrence ties preserved.
// ---------------------------------------------------------------------------
#define CHUNK 64
#define NCHUNK (T_LEN / CHUNK)          // 16
#define CH_FLOATS (CHUNK * N_TAG)       // 1536 floats = 6144 B

__device__ __forceinline__ void cpasync16(uint32_t s, const void* g) {
    asm volatile("cp.async.cg.shared.global [%0], [%1], 16;" :: "r"(s), "l"(g));
}
__device__ __forceinline__ void cpcommit() {
    asm volatile("cp.async.commit_group;");
}
template <int N> __device__ __forceinline__ void cpwait() {
    asm volatile("cp.async.wait_group %0;" :: "n"(N));
}

__global__ void __launch_bounds__(32, 1)
viterbi_kernel(const float* __restrict__ pot,
               const float* __restrict__ trans,
               float* __restrict__ decodedOut) {
    __shared__ __align__(16) float potS[2][CH_FLOATS];       // 12288 B
    __shared__ unsigned char bp_s[(T_LEN - 1) * 32];         // 32736 B

    int b    = blockIdx.x;
    int lane = threadIdx.x;
    int ln   = lane < N_TAG ? lane : (N_TAG - 1);

    const float* potB = pot + (size_t)b * T_LEN * N_TAG;

    float tc[N_TAG];
#pragma unroll
    for (int m = 0; m < N_TAG; m++) tc[m] = trans[m * N_TAG + ln];

    uint32_t potS_addr = (uint32_t)__cvta_generic_to_shared(&potS[0][0]);

    // Issue chunk 0 and chunk 1
#pragma unroll
    for (int j = 0; j < 12; j++)
        cpasync16(potS_addr + j * 512 + lane * 16, potB + j * 128 + lane * 4);
    cpcommit();
#pragma unroll
    for (int j = 0; j < 12; j++)
        cpasync16(potS_addr + 6144 + j * 512 + lane * 16,
                  potB + CH_FLOATS + j * 128 + lane * 4);
    cpcommit();
    cpwait<1>();
    __syncwarp();

    float alpha = potS[0][ln];    // t = 0

    for (int c = 0; c < NCHUNK; c++) {
        const float* pc = potS[c & 1];
        int tstart = (c == 0) ? 1 : 0;
        for (int tt = tstart; tt < CHUNK; tt++) {
            int t = c * CHUNK + tt;
            float pcur = pc[tt * N_TAG + ln];

            float s[N_TAG];
            int   idx[N_TAG];
#pragma unroll
            for (int m = 0; m < N_TAG; m++) {
                s[m]   = __shfl_sync(0xffffffffu, alpha, m) + tc[m];
                idx[m] = m;
            }

            // Contiguous-range tournament; strict '>' keeps first-occurrence
            // ties. Value chain = FMNMX only (4 cyc/level); idx via FSETP+SEL.
#define VCMP(i, j) { bool g = s[j] > s[i];                 \
                     idx[i] = g ? idx[j] : idx[i];          \
                     s[i] = fmaxf(s[i], s[j]); }
#pragma unroll
            for (int st = 1; st < N_TAG; st <<= 1) {
#pragma unroll
                for (int i = 0; i + st < N_TAG; i += 2 * st) VCMP(i, i + st)
            }
#undef VCMP

            alpha = s[0] + pcur;
            bp_s[(t - 1) * 32 + lane] = (unsigned char)idx[0];
        }
        // Refill the buffer just consumed with chunk c+2
        if (c + 2 < NCHUNK) {
            uint32_t dst = potS_addr + (c & 1) * 6144;
            const float* src = potB + (size_t)(c + 2) * CH_FLOATS;
#pragma unroll
            for (int j = 0; j < 12; j++)
                cpasync16(dst + j * 512 + lane * 16, src + j * 128 + lane * 4);
            cpcommit();
            cpwait<1>();
        } else {
            cpwait<0>();
        }
        __syncwarp();
    }

    // last_tag = first-occurrence argmax over lanes 0..23
    float bv = __shfl_sync(0xffffffffu, alpha, 0);
    int   bt = 0;
#pragma unroll
    for (int m = 1; m < N_TAG; m++) {
        float v = __shfl_sync(0xffffffffu, alpha, m);
        if (v > bv) { bv = v; bt = m; }
    }

    if (lane == 0) {
        float* dec = decodedOut + (size_t)b * T_LEN;
        int tag = bt;
        dec[T_LEN - 1] = (float)tag;
        for (int t = T_LEN - 2; t >= 0; t--) {
            tag = bp_s[t * 32 + tag];
            dec[t] = (float)tag;
        }
    }
}

// ---------------------------------------------------------------------------
__global__ void tail_kernel(const float* __restrict__ trans,
                            float* __restrict__ out) {
    int i = threadIdx.x;
    if (i < B_SZ)          out[OFF_LENS + i]  = (float)T_LEN;
    if (i < N_TAG * N_TAG) out[OFF_TRANS + i] = trans[i];
}

// ---------------------------------------------------------------------------
extern "C" void kernel_launch(void* const* d_in, const int* in_sizes, int n_in,
                              void* d_out, int out_size) {
    const float* x     = (const float*)d_in[0];
    const float* W     = (const float*)d_in[1];
    const float* bias  = (const float*)d_in[2];
    const float* trans = (const float*)d_in[3];
    const float* lb    = (const float*)d_in[4];
    const float* rb    = (const float*)d_in[5];

    float* out = (float*)d_out;
    float* pot = out + OFF_POT;

    int smem_bytes = (N_TAG * (D_DIM / 2) + TILE_ROWS * XS_STRIDE) * 8; // 67584
    cudaFuncSetAttribute(gemm_pot_kernel,
                         cudaFuncAttributeMaxDynamicSharedMemorySize, smem_bytes);

    gemm_pot_kernel<<<GRID_GEMM, 256, smem_bytes>>>(x, W, bias, lb, rb, pot);
    tail_kernel<<<1, 640>>>(trans, out);
    viterbi_kernel<<<B_SZ, 32>>>(pot, trans, out);
}